// round 15
// baseline (speedup 1.0000x reference)
#include <cuda_runtime.h>
#include <cuda_bf16.h>
#include <cuda_fp16.h>
#include <cstdint>

#define B_  8
#define C_  64
#define H_  128
#define W_  128
#define O_  64
#define HW_ (H_*W_)
#define K2_ 9

// Scratch (device globals; no allocation allowed)
__device__ __half g_xh[B_*HW_*C_];         // x transposed to [b][h][w][c], fp16
__device__ float  g_off[B_*2*K2_*HW_];     // offsets planar [b][j][h][w] (fp32)
__device__ __half g_wf[K2_*4096];          // weight fp16, swizzled [k][o(64) x c(64)]

// ---------------------------------------------------------------------------
__device__ __forceinline__ uint32_t smem_u32(const void* p) {
    uint32_t a;
    asm("{ .reg .u64 t; cvta.to.shared.u64 t, %1; cvt.u32.u64 %0, t; }"
        : "=r"(a) : "l"(p));
    return a;
}
__device__ __forceinline__ uint32_t cvt2h(float hi, float lo) {
    uint32_t r;
    asm("cvt.rn.f16x2.f32 %0, %1, %2;" : "=r"(r) : "f"(hi), "f"(lo));
    return r;
}
__device__ __forceinline__ float2 h2f2(uint32_t u) {
    __half2 h = *reinterpret_cast<__half2*>(&u);
    return __half22float2(h);
}
__device__ __forceinline__ unsigned long long ffma2(unsigned long long a,
                                                    unsigned long long b,
                                                    unsigned long long c) {
    unsigned long long d;
    asm("fma.rn.f32x2 %0, %1, %2, %3;" : "=l"(d) : "l"(a), "l"(b), "l"(c));
    return d;
}
__device__ __forceinline__ unsigned long long pack2(float x, float y) {
    unsigned long long r;
    asm("mov.b64 %0, {%1, %2};" : "=l"(r) : "f"(x), "f"(y));
    return r;
}
#define LDMX4(r, addr)                                                       \
    asm volatile("ldmatrix.sync.aligned.m8n8.x4.shared.b16 {%0,%1,%2,%3}, [%4];" \
        : "=r"((r)[0]), "=r"((r)[1]), "=r"((r)[2]), "=r"((r)[3]) : "r"(addr))
#define MMA16816H(d, a, b0, b1)                                              \
    asm volatile("mma.sync.aligned.m16n8k16.row.col.f32.f16.f16.f32 "        \
        "{%0,%1,%2,%3}, {%4,%5,%6,%7}, {%8,%9}, {%0,%1,%2,%3};"              \
        : "+f"((d)[0]), "+f"((d)[1]), "+f"((d)[2]), "+f"((d)[3])             \
        : "r"((a)[0]), "r"((a)[1]), "r"((a)[2]), "r"((a)[3]),                \
          "r"(b0), "r"(b1))

// ---------------------------------------------------------------------------
// Kernel 1 (prep v3 fixed): 256px x 64ch fp32 tile in smem, [px][c] layout,
// PSTR=68 -> 16B-aligned rows (LDS.128 legal) and conflict-free einsum loads.
// ALL 256 threads: (1) einsum, 1 px/thread, 9 packed FFMA2 accumulators;
//                  (2) fp16 NHWC transpose sweep.
// ---------------------------------------------------------------------------
#define PSTR 68    // floats per pixel row (16B-aligned rows)

__global__ void __launch_bounds__(256) k_prep(const float* __restrict__ x,
                                              const float* __restrict__ w_off,
                                              const float* __restrict__ b_off) {
    extern __shared__ float sx[];         // [256][PSTR] = 69,632 B
    __shared__ float2 swp[64 * 9];        // packed j-pairs: swp[c*9+i] = (w[2i][c], w[2i+1][c])

    int t   = threadIdx.x;
    int blk = blockIdx.x;                 // 0..511
    int b   = blk >> 6;                   // 64 blocks per batch
    int p0  = (blk & 63) * 256;

    // load x tile: gmem [c][256 px contiguous] -> smem [px][c]
    const float* xb = x + (size_t)b * C_ * HW_ + p0;
#pragma unroll 8
    for (int it = 0; it < 64; it++) {
        int idx = it * 256 + t;
        int c   = idx >> 8;
        int px  = idx & 255;
        sx[px * PSTR + c] = __ldg(xb + (size_t)c * HW_ + px);
    }
    // pack offset weights as j-pairs
    for (int i = t; i < 576; i += 256) {
        int c  = i / 9;
        int jp = i - c * 9;
        swp[c * 9 + jp] = make_float2(__ldg(w_off + (2 * jp) * 64 + c),
                                      __ldg(w_off + (2 * jp + 1) * 64 + c));
    }
    __syncthreads();

    // ---- (1) offset einsum: 1 thread per pixel, LDS.128 channel chunks ----
    {
        int px = t;
        unsigned long long acc[9];
#pragma unroll
        for (int i = 0; i < 9; i++)
            acc[i] = pack2(__ldg(b_off + 2 * i), __ldg(b_off + 2 * i + 1));

        const float* xr = sx + px * PSTR;
#pragma unroll 4
        for (int c4 = 0; c4 < 16; c4++) {
            float4 xv = *(const float4*)(xr + c4 * 4);
            float xf[4] = {xv.x, xv.y, xv.z, xv.w};
#pragma unroll
            for (int u = 0; u < 4; u++) {
                int c = c4 * 4 + u;
                unsigned long long v2 = pack2(xf[u], xf[u]);
                const unsigned long long* wp =
                    (const unsigned long long*)(swp + c * 9);
#pragma unroll
                for (int i = 0; i < 9; i++)
                    acc[i] = ffma2(v2, wp[i], acc[i]);
            }
        }
        float* op = g_off + (size_t)b * 18 * HW_ + p0 + px;
#pragma unroll
        for (int i = 0; i < 9; i++) {
            unsigned long long a = acc[i];
            op[(size_t)(2 * i) * HW_]     = __uint_as_float((unsigned)(a & 0xffffffffULL));
            op[(size_t)(2 * i + 1) * HW_] = __uint_as_float((unsigned)(a >> 32));
        }
    }

    // ---- (2) fp16 NHWC transpose: 256 threads x 4 iters cover 256px x 4cq ----
    {
        int cq = t & 3;                   // 16-channel quarter
        int pb = t >> 2;                  // 0..63
#pragma unroll
        for (int it = 0; it < 4; it++) {
            int px = pb + 64 * it;
            const float* xr = sx + px * PSTR + cq * 16;
            uint32_t v[8];
#pragma unroll
            for (int i = 0; i < 8; i++)
                v[i] = cvt2h(xr[i * 2 + 1], xr[i * 2]);
            char* xout = (char*)g_xh + ((size_t)b * HW_ + p0 + px) * 128 + cq * 32;
            *(uint4*)(xout)      = make_uint4(v[0], v[1], v[2], v[3]);
            *(uint4*)(xout + 16) = make_uint4(v[4], v[5], v[6], v[7]);
        }
    }
}

// ---------------------------------------------------------------------------
// Kernel 2: weights -> fp16, XOR-swizzled rows [o][c]
// ---------------------------------------------------------------------------
__global__ void k_reorder_w(const float* __restrict__ w) {
    int i = blockIdx.x * 256 + threadIdx.x;          // over 9*64*64
    if (i >= K2_ * O_ * C_) return;
    int c = i & 63;
    int r = i >> 6;
    int o = r & 63;
    int k = r >> 6;
    float v = w[((size_t)o * 64 + c) * 9 + k];
    int idx = o * 64 + ((((c >> 3) ^ (o & 7)) << 3)) + (c & 7);
    g_wf[k * 4096 + idx] = __float2half_rn(v);
}

// ---------------------------------------------------------------------------
// Kernel 3: main deformable conv (EXACT R13/R10 structure — known 73us).
// 512 threads, 2 CTAs/SM. One CTA per (b, h): M=128 px, N=64 o, 9 taps.
// Double-buffered A/B -> ONE __syncthreads per tap; all-tap geometry tables.
// ---------------------------------------------------------------------------
#define A0_OFF   0          // A tile fp16 buf0: 16KB
#define A1_OFF   16384      // A tile fp16 buf1: 16KB
#define B0_OFF   32768      // B buf0: 8KB
#define B1_OFF   40960      // B buf1: 8KB
#define PW_OFF   49152      // tables: weights float4 [9][128] = 18KB
#define PA_OFF   67584      // tables: corner byte-offsets uint4 [9][128] = 18KB
#define SMEM_SZ  86016

__global__ void __launch_bounds__(512, 2) k_main(float* __restrict__ out) {
    extern __shared__ char smem[];
    uint32_t sb = smem_u32(smem);
    float4* s_pw = (float4*)(smem + PW_OFF);
    uint4*  s_pa = (uint4*)(smem + PA_OFF);

    int t    = threadIdx.x;
    int lane = t & 31;
    int wid  = t >> 5;
    int h    = blockIdx.x & 127;
    int b    = blockIdx.x >> 7;

    const char* xtb = (const char*)(g_xh + (size_t)b * HW_ * C_);
    const float* offb = g_off + (size_t)b * 18 * HW_ + (size_t)h * W_;

    // ---- Precompute ALL taps' per-pixel bilinear weights + corner offsets ----
    for (int idx = t; idx < 9 * 128; idx += 512) {
        int k = idx >> 7;
        int p = idx & 127;
        int kh = k / 3;
        int kw = k - kh * 3;
        float py = (float)(h - 1 + kh) + __ldg(offb + (size_t)(2 * k) * HW_ + p);
        float px = (float)(p - 1 + kw) + __ldg(offb + (size_t)(2 * k + 1) * HW_ + p);
        int y0 = __float2int_rd(py);
        int x0 = __float2int_rd(px);
        float wy1 = py - (float)y0, wx1 = px - (float)x0;
        float wy0 = 1.0f - wy1,     wx0 = 1.0f - wx1;
        int y1 = y0 + 1, x1 = x0 + 1;
        bool vy0 = (unsigned)y0 < (unsigned)H_;
        bool vy1 = (unsigned)y1 < (unsigned)H_;
        bool vx0 = (unsigned)x0 < (unsigned)W_;
        bool vx1 = (unsigned)x1 < (unsigned)W_;
        int y0c = min(max(y0, 0), H_ - 1), y1c = min(max(y1, 0), H_ - 1);
        int x0c = min(max(x0, 0), W_ - 1), x1c = min(max(x1, 0), W_ - 1);
        float4 w4;
        w4.x = (vy0 && vx0) ? wy0 * wx0 : 0.0f;
        w4.y = (vy0 && vx1) ? wy0 * wx1 : 0.0f;
        w4.z = (vy1 && vx0) ? wy1 * wx0 : 0.0f;
        w4.w = (vy1 && vx1) ? wy1 * wx1 : 0.0f;
        uint4 a4;
        a4.x = (uint32_t)((y0c * W_ + x0c) << 7);   // *64ch*2B
        a4.y = (uint32_t)((y0c * W_ + x1c) << 7);
        a4.z = (uint32_t)((y1c * W_ + x0c) << 7);
        a4.w = (uint32_t)((y1c * W_ + x1c) << 7);
        s_pw[idx] = w4;
        s_pa[idx] = a4;
    }

    float acc[4][4];
#pragma unroll
    for (int nt = 0; nt < 4; nt++)
#pragma unroll
        for (int j = 0; j < 4; j++) acc[nt][j] = 0.0f;

    // Phase-A mapping: 8-channel granule per thread
    const int pa_cg = t & 7;     // granule 0..7 (16B of fp16 = 8 channels)
    const int pa_p0 = t >> 3;    // pixel within pass (0..63)
    // Warp tile mapping (16 warps)
    const int wm = wid & 7;      // px group: 16*wm .. +15
    const int wn = wid >> 3;     // o  group: 32*wn .. +31
    // ldmatrix lane roles
    const int a_r  = lane & 15;
    const int a_q  = lane >> 4;
    const int b_or = (lane & 7) + ((lane >> 4) << 3);
    const int b_qb = (lane >> 3) & 1;

    __syncthreads();   // tables ready

    for (int k = 0; k < 9; k++) {
        const int buf = k & 1;
        char* a_buf = smem + (buf ? A1_OFF : A0_OFF);
        char* b_buf = smem + (buf ? B1_OFF : B0_OFF);

        // prefetch B_k into registers (hidden behind sampling)
        uint4 wb;
        {
            const uint4* sh = (const uint4*)g_wf + (size_t)k * 512;
            wb = __ldg(sh + t);
        }

        // ---- Phase A: fp16 gather + fp32 bilinear -> fp16 A tile (buf) ----
        const float4* pwk = s_pw + k * 128;
        const uint4*  pak = s_pa + k * 128;
#pragma unroll
        for (int pass = 0; pass < 2; pass++) {
            int p = pass * 64 + pa_p0;
            float4 w4 = pwk[p];
            uint4  a4 = pak[p];
            int cb = pa_cg * 16;   // granule byte offset (8 fp16 channels)

            uint4 u0 = __ldg((const uint4*)(xtb + a4.x + cb));
            uint4 u1 = __ldg((const uint4*)(xtb + a4.y + cb));
            uint4 u2 = __ldg((const uint4*)(xtb + a4.z + cb));
            uint4 u3 = __ldg((const uint4*)(xtb + a4.w + cb));

            uint32_t c0a[4] = {u0.x, u0.y, u0.z, u0.w};
            uint32_t c1a[4] = {u1.x, u1.y, u1.z, u1.w};
            uint32_t c2a[4] = {u2.x, u2.y, u2.z, u2.w};
            uint32_t c3a[4] = {u3.x, u3.y, u3.z, u3.w};

            float2 s[4];
#pragma unroll
            for (int j = 0; j < 4; j++) {
                float2 f = h2f2(c0a[j]);
                s[j].x = w4.x * f.x;
                s[j].y = w4.x * f.y;
            }
#pragma unroll
            for (int j = 0; j < 4; j++) {
                float2 f = h2f2(c1a[j]);
                s[j].x = fmaf(w4.y, f.x, s[j].x);
                s[j].y = fmaf(w4.y, f.y, s[j].y);
            }
#pragma unroll
            for (int j = 0; j < 4; j++) {
                float2 f = h2f2(c2a[j]);
                s[j].x = fmaf(w4.z, f.x, s[j].x);
                s[j].y = fmaf(w4.z, f.y, s[j].y);
            }
#pragma unroll
            for (int j = 0; j < 4; j++) {
                float2 f = h2f2(c3a[j]);
                s[j].x = fmaf(w4.w, f.x, s[j].x);
                s[j].y = fmaf(w4.w, f.y, s[j].y);
            }

            uint4 o;
            o.x = cvt2h(s[0].y, s[0].x);   // low half = lower channel
            o.y = cvt2h(s[1].y, s[1].x);
            o.z = cvt2h(s[2].y, s[2].x);
            o.w = cvt2h(s[3].y, s[3].x);

            int chunk = pa_cg ^ (p & 7);
            *(uint4*)(a_buf + p * 128 + chunk * 16) = o;
        }

        // store prefetched B (pre-swizzled layout): 512 threads x 16B = 8KB
        ((uint4*)b_buf)[t] = wb;

        __syncthreads();   // A(k), B(k) ready; also releases buf for k+2's writes

        // ---- Phase B: HMMA over 4 k-tiles, single fp16 term ----
        uint32_t a_base = sb + (buf ? A1_OFF : A0_OFF);
        uint32_t b_base = sb + (buf ? B1_OFF : B0_OFF);
#pragma unroll
        for (int kt = 0; kt < 4; kt++) {
            uint32_t af[4];
            {
                int row = wm * 16 + a_r;
                uint32_t ad = a_base + row * 128 +
                              (((2 * kt + a_q) ^ (a_r & 7)) * 16);
                LDMX4(af, ad);
            }
            uint32_t bf[2][4];
#pragma unroll
            for (int j = 0; j < 2; j++) {
                int o = wn * 32 + j * 16 + b_or;
                uint32_t bd = b_base + o * 128 +
                              (((2 * kt + b_qb) ^ (o & 7)) * 16);
                LDMX4(bf[j], bd);
            }
#pragma unroll
            for (int nt = 0; nt < 4; nt++) {
                const uint32_t* bp = &bf[nt >> 1][(nt & 1) * 2];
                MMA16816H(acc[nt], af, bp[0], bp[1]);
            }
        }
    }

    // ---- Epilogue: direct STG ----
    {
        int px = wm * 16 + (lane >> 2);
#pragma unroll
        for (int nt = 0; nt < 4; nt++) {
            int o0 = wn * 32 + nt * 8 + 2 * (lane & 3);
            float* ob = out + ((size_t)(b * 64 + o0)) * HW_ + (size_t)h * W_;
            ob[px]           = acc[nt][0];
            ob[HW_ + px]     = acc[nt][1];
            ob[px + 8]       = acc[nt][2];
            ob[HW_ + px + 8] = acc[nt][3];
        }
    }
}

// ---------------------------------------------------------------------------
extern "C" void kernel_launch(void* const* d_in, const int* in_sizes, int n_in,
                              void* d_out, int out_size) {
    const float* x     = (const float*)d_in[0];   // (8,64,128,128)
    const float* wght  = (const float*)d_in[1];   // (64,64,3,3)
    const float* w_off = (const float*)d_in[2];   // (18,64)
    const float* b_off = (const float*)d_in[3];   // (18,)
    float* out = (float*)d_out;                   // (8,64,128,128)

    const int prep_smem = 256 * PSTR * (int)sizeof(float);
    cudaFuncSetAttribute(k_prep, cudaFuncAttributeMaxDynamicSharedMemorySize,
                         prep_smem);
    k_prep<<<B_ * HW_ / 256, 256, prep_smem>>>(x, w_off, b_off);
    k_reorder_w<<<(K2_ * O_ * C_ + 255) / 256, 256>>>(wght);

    cudaFuncSetAttribute(k_main, cudaFuncAttributeMaxDynamicSharedMemorySize,
                         SMEM_SZ);
    k_main<<<B_ * H_, 512, SMEM_SZ>>>(out);
}

// round 16
// speedup vs baseline: 1.0044x; 1.0044x over previous
#include <cuda_runtime.h>
#include <cuda_bf16.h>
#include <cuda_fp16.h>
#include <cstdint>

#define B_  8
#define C_  64
#define H_  128
#define W_  128
#define O_  64
#define HW_ (H_*W_)
#define K2_ 9

// Scratch (device globals; no allocation allowed)
__device__ __half g_xh[B_*HW_*C_];         // x transposed to [b][h][w][c], fp16
__device__ float  g_off[B_*2*K2_*HW_];     // offsets planar [b][j][h][w] (fp32)
__device__ __half g_wf[K2_*4096];          // weight fp16, swizzled [k][o(64) x c(64)]

// ---------------------------------------------------------------------------
__device__ __forceinline__ uint32_t smem_u32(const void* p) {
    uint32_t a;
    asm("{ .reg .u64 t; cvta.to.shared.u64 t, %1; cvt.u32.u64 %0, t; }"
        : "=r"(a) : "l"(p));
    return a;
}
__device__ __forceinline__ uint32_t cvt2h(float hi, float lo) {
    uint32_t r;
    asm("cvt.rn.f16x2.f32 %0, %1, %2;" : "=r"(r) : "f"(hi), "f"(lo));
    return r;
}
__device__ __forceinline__ float2 h2f2(uint32_t u) {
    __half2 h = *reinterpret_cast<__half2*>(&u);
    return __half22float2(h);
}
__device__ __forceinline__ unsigned long long ffma2(unsigned long long a,
                                                    unsigned long long b,
                                                    unsigned long long c) {
    unsigned long long d;
    asm("fma.rn.f32x2 %0, %1, %2, %3;" : "=l"(d) : "l"(a), "l"(b), "l"(c));
    return d;
}
__device__ __forceinline__ unsigned long long pack2(float x, float y) {
    unsigned long long r;
    asm("mov.b64 %0, {%1, %2};" : "=l"(r) : "f"(x), "f"(y));
    return r;
}
#define LDMX4(r, addr)                                                       \
    asm volatile("ldmatrix.sync.aligned.m8n8.x4.shared.b16 {%0,%1,%2,%3}, [%4];" \
        : "=r"((r)[0]), "=r"((r)[1]), "=r"((r)[2]), "=r"((r)[3]) : "r"(addr))
#define MMA16816H(d, a, b0, b1)                                              \
    asm volatile("mma.sync.aligned.m16n8k16.row.col.f32.f16.f16.f32 "        \
        "{%0,%1,%2,%3}, {%4,%5,%6,%7}, {%8,%9}, {%0,%1,%2,%3};"              \
        : "+f"((d)[0]), "+f"((d)[1]), "+f"((d)[2]), "+f"((d)[3])             \
        : "r"((a)[0]), "r"((a)[1]), "r"((a)[2]), "r"((a)[3]),                \
          "r"(b0), "r"(b1))

// ---------------------------------------------------------------------------
// Kernel 1 (prep v4): 128px x 64ch fp32 tile in smem (R13 footprint, 39KB),
// but the einsum is split across LANE PAIRS: thread 2p does channels 0..31 of
// pixel p, thread 2p+1 does 32..63; partial sums combine via shfl_xor(1).
// All 256 threads then sweep the fp16 NHWC transpose. Reorder-w blocks are
// fused into the same grid (blk >= PREP_BLKS).
// ---------------------------------------------------------------------------
#define PSTR 133   // smem row stride (floats)
#define PREP_BLKS (B_ * HW_ / 128)     // 1024

__global__ void __launch_bounds__(256) k_prep(const float* __restrict__ x,
                                              const float* __restrict__ w_off,
                                              const float* __restrict__ b_off,
                                              const float* __restrict__ wght) {
    __shared__ float  sx[64 * PSTR];      // ~34KB
    __shared__ float2 swp[64 * 9];        // packed j-pairs: swp[c*9+i] = (w[2i][c], w[2i+1][c])

    int t   = threadIdx.x;
    int blk = blockIdx.x;

    // ---- fused weight reorder blocks ----
    if (blk >= PREP_BLKS) {
        int k = blk - PREP_BLKS;          // 0..8
#pragma unroll 4
        for (int i = t; i < 4096; i += 256) {
            int c = i & 63;
            int o = i >> 6;
            float v = __ldg(wght + ((size_t)o * 64 + c) * 9 + k);
            int idx = o * 64 + ((((c >> 3) ^ (o & 7)) << 3)) + (c & 7);
            g_wf[k * 4096 + idx] = __float2half_rn(v);
        }
        return;
    }

    int b   = blk >> 7;                   // 128 blocks per batch
    int p0  = (blk & 127) * 128;

    // load x tile (coalesced scalar rows)
    const float* xb = x + (size_t)b * C_ * HW_ + p0;
#pragma unroll 8
    for (int it = 0; it < 32; it++) {
        int idx = it * 256 + t;
        int c   = idx >> 7;
        int px  = idx & 127;
        sx[c * PSTR + px] = __ldg(xb + (size_t)c * HW_ + px);
    }
    // pack offset weights as j-pairs
    for (int i = t; i < 576; i += 256) {
        int c  = i / 9;
        int jp = i - c * 9;
        swp[c * 9 + jp] = make_float2(__ldg(w_off + (2 * jp) * 64 + c),
                                      __ldg(w_off + (2 * jp + 1) * 64 + c));
    }
    __syncthreads();

    // ---- (1) einsum: lane pair per pixel (32 channels each), shfl combine ----
    {
        int px   = t >> 1;
        int half = t & 1;
        int c0   = half << 5;             // 0 or 32

        unsigned long long acc[9];
#pragma unroll
        for (int i = 0; i < 9; i++)
            acc[i] = half ? 0ULL
                          : pack2(__ldg(b_off + 2 * i), __ldg(b_off + 2 * i + 1));

#pragma unroll 4
        for (int c = 0; c < 32; c++) {
            int cc = c0 + c;
            float v = sx[cc * PSTR + px];
            unsigned long long v2 = pack2(v, v);
            const unsigned long long* wp =
                (const unsigned long long*)(swp + cc * 9);
#pragma unroll
            for (int i = 0; i < 9; i++)
                acc[i] = ffma2(v2, wp[i], acc[i]);
        }

        // combine lane pairs and write: even lane writes j=2i, odd j=2i+1
        float* op = g_off + (size_t)b * 18 * HW_ + p0 + px;
#pragma unroll
        for (int i = 0; i < 9; i++) {
            float lo = __uint_as_float((unsigned)(acc[i] & 0xffffffffULL));
            float hi = __uint_as_float((unsigned)(acc[i] >> 32));
            lo += __shfl_xor_sync(0xffffffffu, lo, 1);
            hi += __shfl_xor_sync(0xffffffffu, hi, 1);
            if (half == 0) op[(size_t)(2 * i) * HW_]     = lo;
            else           op[(size_t)(2 * i + 1) * HW_] = hi;
        }
    }

    // ---- (2) fp16 NHWC transpose: 256 threads x 2 iters cover 128px x 4cq ----
    {
        int cq = t & 3;                   // 16-channel quarter
        int pb = t >> 2;                  // 0..63
#pragma unroll
        for (int it = 0; it < 2; it++) {
            int px = pb + 64 * it;
            uint32_t v[8];
#pragma unroll
            for (int i = 0; i < 8; i++) {
                int c = cq * 16 + i * 2;
                v[i] = cvt2h(sx[(c + 1) * PSTR + px], sx[c * PSTR + px]);
            }
            char* xout = (char*)g_xh + ((size_t)b * HW_ + p0 + px) * 128 + cq * 32;
            *(uint4*)(xout)      = make_uint4(v[0], v[1], v[2], v[3]);
            *(uint4*)(xout + 16) = make_uint4(v[4], v[5], v[6], v[7]);
        }
    }
}

// ---------------------------------------------------------------------------
// Kernel 2: main deformable conv (EXACT R13/R10 structure — known 73us).
// 512 threads, 2 CTAs/SM. One CTA per (b, h): M=128 px, N=64 o, 9 taps.
// Double-buffered A/B -> ONE __syncthreads per tap; all-tap geometry tables.
// ---------------------------------------------------------------------------
#define A0_OFF   0          // A tile fp16 buf0: 16KB
#define A1_OFF   16384      // A tile fp16 buf1: 16KB
#define B0_OFF   32768      // B buf0: 8KB
#define B1_OFF   40960      // B buf1: 8KB
#define PW_OFF   49152      // tables: weights float4 [9][128] = 18KB
#define PA_OFF   67584      // tables: corner byte-offsets uint4 [9][128] = 18KB
#define SMEM_SZ  86016

__global__ void __launch_bounds__(512, 2) k_main(float* __restrict__ out) {
    extern __shared__ char smem[];
    uint32_t sb = smem_u32(smem);
    float4* s_pw = (float4*)(smem + PW_OFF);
    uint4*  s_pa = (uint4*)(smem + PA_OFF);

    int t    = threadIdx.x;
    int lane = t & 31;
    int wid  = t >> 5;
    int h    = blockIdx.x & 127;
    int b    = blockIdx.x >> 7;

    const char* xtb = (const char*)(g_xh + (size_t)b * HW_ * C_);
    const float* offb = g_off + (size_t)b * 18 * HW_ + (size_t)h * W_;

    // ---- Precompute ALL taps' per-pixel bilinear weights + corner offsets ----
    for (int idx = t; idx < 9 * 128; idx += 512) {
        int k = idx >> 7;
        int p = idx & 127;
        int kh = k / 3;
        int kw = k - kh * 3;
        float py = (float)(h - 1 + kh) + __ldg(offb + (size_t)(2 * k) * HW_ + p);
        float px = (float)(p - 1 + kw) + __ldg(offb + (size_t)(2 * k + 1) * HW_ + p);
        int y0 = __float2int_rd(py);
        int x0 = __float2int_rd(px);
        float wy1 = py - (float)y0, wx1 = px - (float)x0;
        float wy0 = 1.0f - wy1,     wx0 = 1.0f - wx1;
        int y1 = y0 + 1, x1 = x0 + 1;
        bool vy0 = (unsigned)y0 < (unsigned)H_;
        bool vy1 = (unsigned)y1 < (unsigned)H_;
        bool vx0 = (unsigned)x0 < (unsigned)W_;
        bool vx1 = (unsigned)x1 < (unsigned)W_;
        int y0c = min(max(y0, 0), H_ - 1), y1c = min(max(y1, 0), H_ - 1);
        int x0c = min(max(x0, 0), W_ - 1), x1c = min(max(x1, 0), W_ - 1);
        float4 w4;
        w4.x = (vy0 && vx0) ? wy0 * wx0 : 0.0f;
        w4.y = (vy0 && vx1) ? wy0 * wx1 : 0.0f;
        w4.z = (vy1 && vx0) ? wy1 * wx0 : 0.0f;
        w4.w = (vy1 && vx1) ? wy1 * wx1 : 0.0f;
        uint4 a4;
        a4.x = (uint32_t)((y0c * W_ + x0c) << 7);   // *64ch*2B
        a4.y = (uint32_t)((y0c * W_ + x1c) << 7);
        a4.z = (uint32_t)((y1c * W_ + x0c) << 7);
        a4.w = (uint32_t)((y1c * W_ + x1c) << 7);
        s_pw[idx] = w4;
        s_pa[idx] = a4;
    }

    float acc[4][4];
#pragma unroll
    for (int nt = 0; nt < 4; nt++)
#pragma unroll
        for (int j = 0; j < 4; j++) acc[nt][j] = 0.0f;

    // Phase-A mapping: 8-channel granule per thread
    const int pa_cg = t & 7;     // granule 0..7 (16B of fp16 = 8 channels)
    const int pa_p0 = t >> 3;    // pixel within pass (0..63)
    // Warp tile mapping (16 warps)
    const int wm = wid & 7;      // px group: 16*wm .. +15
    const int wn = wid >> 3;     // o  group: 32*wn .. +31
    // ldmatrix lane roles
    const int a_r  = lane & 15;
    const int a_q  = lane >> 4;
    const int b_or = (lane & 7) + ((lane >> 4) << 3);
    const int b_qb = (lane >> 3) & 1;

    __syncthreads();   // tables ready

    for (int k = 0; k < 9; k++) {
        const int buf = k & 1;
        char* a_buf = smem + (buf ? A1_OFF : A0_OFF);
        char* b_buf = smem + (buf ? B1_OFF : B0_OFF);

        // prefetch B_k into registers (hidden behind sampling)
        uint4 wb;
        {
            const uint4* sh = (const uint4*)g_wf + (size_t)k * 512;
            wb = __ldg(sh + t);
        }

        // ---- Phase A: fp16 gather + fp32 bilinear -> fp16 A tile (buf) ----
        const float4* pwk = s_pw + k * 128;
        const uint4*  pak = s_pa + k * 128;
#pragma unroll
        for (int pass = 0; pass < 2; pass++) {
            int p = pass * 64 + pa_p0;
            float4 w4 = pwk[p];
            uint4  a4 = pak[p];
            int cb = pa_cg * 16;   // granule byte offset (8 fp16 channels)

            uint4 u0 = __ldg((const uint4*)(xtb + a4.x + cb));
            uint4 u1 = __ldg((const uint4*)(xtb + a4.y + cb));
            uint4 u2 = __ldg((const uint4*)(xtb + a4.z + cb));
            uint4 u3 = __ldg((const uint4*)(xtb + a4.w + cb));

            uint32_t c0a[4] = {u0.x, u0.y, u0.z, u0.w};
            uint32_t c1a[4] = {u1.x, u1.y, u1.z, u1.w};
            uint32_t c2a[4] = {u2.x, u2.y, u2.z, u2.w};
            uint32_t c3a[4] = {u3.x, u3.y, u3.z, u3.w};

            float2 s[4];
#pragma unroll
            for (int j = 0; j < 4; j++) {
                float2 f = h2f2(c0a[j]);
                s[j].x = w4.x * f.x;
                s[j].y = w4.x * f.y;
            }
#pragma unroll
            for (int j = 0; j < 4; j++) {
                float2 f = h2f2(c1a[j]);
                s[j].x = fmaf(w4.y, f.x, s[j].x);
                s[j].y = fmaf(w4.y, f.y, s[j].y);
            }
#pragma unroll
            for (int j = 0; j < 4; j++) {
                float2 f = h2f2(c2a[j]);
                s[j].x = fmaf(w4.z, f.x, s[j].x);
                s[j].y = fmaf(w4.z, f.y, s[j].y);
            }
#pragma unroll
            for (int j = 0; j < 4; j++) {
                float2 f = h2f2(c3a[j]);
                s[j].x = fmaf(w4.w, f.x, s[j].x);
                s[j].y = fmaf(w4.w, f.y, s[j].y);
            }

            uint4 o;
            o.x = cvt2h(s[0].y, s[0].x);   // low half = lower channel
            o.y = cvt2h(s[1].y, s[1].x);
            o.z = cvt2h(s[2].y, s[2].x);
            o.w = cvt2h(s[3].y, s[3].x);

            int chunk = pa_cg ^ (p & 7);
            *(uint4*)(a_buf + p * 128 + chunk * 16) = o;
        }

        // store prefetched B (pre-swizzled layout): 512 threads x 16B = 8KB
        ((uint4*)b_buf)[t] = wb;

        __syncthreads();   // A(k), B(k) ready; also releases buf for k+2's writes

        // ---- Phase B: HMMA over 4 k-tiles, single fp16 term ----
        uint32_t a_base = sb + (buf ? A1_OFF : A0_OFF);
        uint32_t b_base = sb + (buf ? B1_OFF : B0_OFF);
#pragma unroll
        for (int kt = 0; kt < 4; kt++) {
            uint32_t af[4];
            {
                int row = wm * 16 + a_r;
                uint32_t ad = a_base + row * 128 +
                              (((2 * kt + a_q) ^ (a_r & 7)) * 16);
                LDMX4(af, ad);
            }
            uint32_t bf[2][4];
#pragma unroll
            for (int j = 0; j < 2; j++) {
                int o = wn * 32 + j * 16 + b_or;
                uint32_t bd = b_base + o * 128 +
                              (((2 * kt + b_qb) ^ (o & 7)) * 16);
                LDMX4(bf[j], bd);
            }
#pragma unroll
            for (int nt = 0; nt < 4; nt++) {
                const uint32_t* bp = &bf[nt >> 1][(nt & 1) * 2];
                MMA16816H(acc[nt], af, bp[0], bp[1]);
            }
        }
    }

    // ---- Epilogue: direct STG ----
    {
        int px = wm * 16 + (lane >> 2);
#pragma unroll
        for (int nt = 0; nt < 4; nt++) {
            int o0 = wn * 32 + nt * 8 + 2 * (lane & 3);
            float* ob = out + ((size_t)(b * 64 + o0)) * HW_ + (size_t)h * W_;
            ob[px]           = acc[nt][0];
            ob[HW_ + px]     = acc[nt][1];
            ob[px + 8]       = acc[nt][2];
            ob[HW_ + px + 8] = acc[nt][3];
        }
    }
}

// ---------------------------------------------------------------------------
extern "C" void kernel_launch(void* const* d_in, const int* in_sizes, int n_in,
                              void* d_out, int out_size) {
    const float* x     = (const float*)d_in[0];   // (8,64,128,128)
    const float* wght  = (const float*)d_in[1];   // (64,64,3,3)
    const float* w_off = (const float*)d_in[2];   // (18,64)
    const float* b_off = (const float*)d_in[3];   // (18,)
    float* out = (float*)d_out;                   // (8,64,128,128)

    k_prep<<<PREP_BLKS + K2_, 256>>>(x, w_off, b_off, wght);

    cudaFuncSetAttribute(k_main, cudaFuncAttributeMaxDynamicSharedMemorySize,
                         SMEM_SZ);
    k_main<<<B_ * H_, 512, SMEM_SZ>>>(out);
}

// round 17
// speedup vs baseline: 1.1036x; 1.0988x over previous
#include <cuda_runtime.h>
#include <cuda_bf16.h>
#include <cuda_fp16.h>
#include <cstdint>

#define B_  8
#define C_  64
#define H_  128
#define W_  128
#define O_  64
#define HW_ (H_*W_)
#define K2_ 9

// Scratch (device globals; no allocation allowed)
__device__ __half g_xh[B_*HW_*C_];         // x transposed to [b][h][w][c], fp16
__device__ float  g_off[B_*2*K2_*HW_];     // offsets planar [b][j][h][w] (fp32)
__device__ __half g_wf[K2_*4096];          // weight fp16, swizzled [k][o(64) x c(64)]

// ---------------------------------------------------------------------------
__device__ __forceinline__ uint32_t smem_u32(const void* p) {
    uint32_t a;
    asm("{ .reg .u64 t; cvta.to.shared.u64 t, %1; cvt.u32.u64 %0, t; }"
        : "=r"(a) : "l"(p));
    return a;
}
__device__ __forceinline__ uint32_t cvt2h(float hi, float lo) {
    uint32_t r;
    asm("cvt.rn.f16x2.f32 %0, %1, %2;" : "=r"(r) : "f"(hi), "f"(lo));
    return r;
}
__device__ __forceinline__ float2 h2f2(uint32_t u) {
    __half2 h = *reinterpret_cast<__half2*>(&u);
    return __half22float2(h);
}
__device__ __forceinline__ unsigned long long ffma2(unsigned long long a,
                                                    unsigned long long b,
                                                    unsigned long long c) {
    unsigned long long d;
    asm("fma.rn.f32x2 %0, %1, %2, %3;" : "=l"(d) : "l"(a), "l"(b), "l"(c));
    return d;
}
__device__ __forceinline__ unsigned long long pack2(float x, float y) {
    unsigned long long r;
    asm("mov.b64 %0, {%1, %2};" : "=l"(r) : "f"(x), "f"(y));
    return r;
}
#define LDMX4(r, addr)                                                       \
    asm volatile("ldmatrix.sync.aligned.m8n8.x4.shared.b16 {%0,%1,%2,%3}, [%4];" \
        : "=r"((r)[0]), "=r"((r)[1]), "=r"((r)[2]), "=r"((r)[3]) : "r"(addr))
#define MMA16816H(d, a, b0, b1)                                              \
    asm volatile("mma.sync.aligned.m16n8k16.row.col.f32.f16.f16.f32 "        \
        "{%0,%1,%2,%3}, {%4,%5,%6,%7}, {%8,%9}, {%0,%1,%2,%3};"              \
        : "+f"((d)[0]), "+f"((d)[1]), "+f"((d)[2]), "+f"((d)[3])             \
        : "r"((a)[0]), "r"((a)[1]), "r"((a)[2]), "r"((a)[3]),                \
          "r"(b0), "r"(b1))

// ---------------------------------------------------------------------------
// Kernel 1 (prep = R13 byte-exact + fused weight reorder blocks).
// 128px x 64ch fp32 tile in smem. Threads 0-127: offset einsum (1 px/thread,
// FFMA2 packed j-pairs). Threads 128-255: fp16 NHWC transpose writes.
// Blocks >= PREP_BLKS do the weight fp16 reorder instead.
// ---------------------------------------------------------------------------
#define PSTR 133   // smem row stride (floats)
#define PREP_BLKS (B_ * HW_ / 128)     // 1024

__global__ void __launch_bounds__(256) k_prep(const float* __restrict__ x,
                                              const float* __restrict__ w_off,
                                              const float* __restrict__ b_off,
                                              const float* __restrict__ wght) {
    __shared__ float  sx[64 * PSTR];      // ~34KB
    __shared__ float2 swp[64 * 9];        // packed j-pairs: swp[c*9+i] = (w[2i][c], w[2i+1][c])

    int t   = threadIdx.x;
    int blk = blockIdx.x;

    // ---- fused weight reorder blocks ----
    if (blk >= PREP_BLKS) {
        int k = blk - PREP_BLKS;          // 0..8
#pragma unroll 4
        for (int i = t; i < 4096; i += 256) {
            int c = i & 63;
            int o = i >> 6;
            float v = __ldg(wght + ((size_t)o * 64 + c) * 9 + k);
            int idx = o * 64 + ((((c >> 3) ^ (o & 7)) << 3)) + (c & 7);
            g_wf[k * 4096 + idx] = __float2half_rn(v);
        }
        return;
    }

    int b   = blk >> 7;                   // 128 blocks per batch
    int p0  = (blk & 127) * 128;

    // load x tile (coalesced scalar rows)
    const float* xb = x + (size_t)b * C_ * HW_ + p0;
#pragma unroll 8
    for (int it = 0; it < 32; it++) {
        int idx = it * 256 + t;
        int c   = idx >> 7;
        int px  = idx & 127;
        sx[c * PSTR + px] = __ldg(xb + (size_t)c * HW_ + px);
    }
    // pack offset weights as j-pairs
    for (int i = t; i < 576; i += 256) {
        int c  = i / 9;
        int jp = i - c * 9;
        swp[c * 9 + jp] = make_float2(__ldg(w_off + (2 * jp) * 64 + c),
                                      __ldg(w_off + (2 * jp + 1) * 64 + c));
    }
    __syncthreads();

    if (t < 128) {
        // ---- offset einsum: 1 thread per pixel, 9 packed accumulators ----
        int px = t;
        unsigned long long acc[9];
#pragma unroll
        for (int i = 0; i < 9; i++)
            acc[i] = pack2(__ldg(b_off + 2 * i), __ldg(b_off + 2 * i + 1));

#pragma unroll 4
        for (int c = 0; c < 64; c++) {
            float v = sx[c * PSTR + px];
            unsigned long long v2 = pack2(v, v);
            const unsigned long long* wp =
                (const unsigned long long*)(swp + c * 9);
#pragma unroll
            for (int i = 0; i < 9; i++)
                acc[i] = ffma2(v2, wp[i], acc[i]);
        }
        float* op = g_off + (size_t)b * 18 * HW_ + p0 + px;
#pragma unroll
        for (int i = 0; i < 9; i++) {
            unsigned long long a = acc[i];
            op[(size_t)(2 * i) * HW_]     = __uint_as_float((unsigned)(a & 0xffffffffULL));
            op[(size_t)(2 * i + 1) * HW_] = __uint_as_float((unsigned)(a >> 32));
        }
    } else {
        // ---- fp16 NHWC transpose: 128 threads cover 128 px x 4 cq over 4 iters ----
        int i2 = t - 128;
        int cq = i2 & 3;                  // 16-channel quarter
        int pb = i2 >> 2;                 // 0..31
#pragma unroll
        for (int it = 0; it < 4; it++) {
            int px = pb + 32 * it;
            uint32_t v[8];
#pragma unroll
            for (int i = 0; i < 8; i++) {
                int c = cq * 16 + i * 2;
                v[i] = cvt2h(sx[(c + 1) * PSTR + px], sx[c * PSTR + px]);
            }
            char* xout = (char*)g_xh + ((size_t)b * HW_ + p0 + px) * 128 + cq * 32;
            *(uint4*)(xout)      = make_uint4(v[0], v[1], v[2], v[3]);
            *(uint4*)(xout + 16) = make_uint4(v[4], v[5], v[6], v[7]);
        }
    }
}

// ---------------------------------------------------------------------------
// Kernel 2: main deformable conv (EXACT R13/R10 structure).
// 512 threads, 2 CTAs/SM. One CTA per (b, h): M=128 px, N=64 o, 9 taps.
// Double-buffered A/B -> ONE __syncthreads per tap; all-tap geometry tables.
// ---------------------------------------------------------------------------
#define A0_OFF   0          // A tile fp16 buf0: 16KB
#define A1_OFF   16384      // A tile fp16 buf1: 16KB
#define B0_OFF   32768      // B buf0: 8KB
#define B1_OFF   40960      // B buf1: 8KB
#define PW_OFF   49152      // tables: weights float4 [9][128] = 18KB
#define PA_OFF   67584      // tables: corner byte-offsets uint4 [9][128] = 18KB
#define SMEM_SZ  86016

__global__ void __launch_bounds__(512, 2) k_main(float* __restrict__ out) {
    extern __shared__ char smem[];
    uint32_t sb = smem_u32(smem);
    float4* s_pw = (float4*)(smem + PW_OFF);
    uint4*  s_pa = (uint4*)(smem + PA_OFF);

    int t    = threadIdx.x;
    int lane = t & 31;
    int wid  = t >> 5;
    int h    = blockIdx.x & 127;
    int b    = blockIdx.x >> 7;

    const char* xtb = (const char*)(g_xh + (size_t)b * HW_ * C_);
    const float* offb = g_off + (size_t)b * 18 * HW_ + (size_t)h * W_;

    // ---- Precompute ALL taps' per-pixel bilinear weights + corner offsets ----
    for (int idx = t; idx < 9 * 128; idx += 512) {
        int k = idx >> 7;
        int p = idx & 127;
        int kh = k / 3;
        int kw = k - kh * 3;
        float py = (float)(h - 1 + kh) + __ldg(offb + (size_t)(2 * k) * HW_ + p);
        float px = (float)(p - 1 + kw) + __ldg(offb + (size_t)(2 * k + 1) * HW_ + p);
        int y0 = __float2int_rd(py);
        int x0 = __float2int_rd(px);
        float wy1 = py - (float)y0, wx1 = px - (float)x0;
        float wy0 = 1.0f - wy1,     wx0 = 1.0f - wx1;
        int y1 = y0 + 1, x1 = x0 + 1;
        bool vy0 = (unsigned)y0 < (unsigned)H_;
        bool vy1 = (unsigned)y1 < (unsigned)H_;
        bool vx0 = (unsigned)x0 < (unsigned)W_;
        bool vx1 = (unsigned)x1 < (unsigned)W_;
        int y0c = min(max(y0, 0), H_ - 1), y1c = min(max(y1, 0), H_ - 1);
        int x0c = min(max(x0, 0), W_ - 1), x1c = min(max(x1, 0), W_ - 1);
        float4 w4;
        w4.x = (vy0 && vx0) ? wy0 * wx0 : 0.0f;
        w4.y = (vy0 && vx1) ? wy0 * wx1 : 0.0f;
        w4.z = (vy1 && vx0) ? wy1 * wx0 : 0.0f;
        w4.w = (vy1 && vx1) ? wy1 * wx1 : 0.0f;
        uint4 a4;
        a4.x = (uint32_t)((y0c * W_ + x0c) << 7);   // *64ch*2B
        a4.y = (uint32_t)((y0c * W_ + x1c) << 7);
        a4.z = (uint32_t)((y1c * W_ + x0c) << 7);
        a4.w = (uint32_t)((y1c * W_ + x1c) << 7);
        s_pw[idx] = w4;
        s_pa[idx] = a4;
    }

    float acc[4][4];
#pragma unroll
    for (int nt = 0; nt < 4; nt++)
#pragma unroll
        for (int j = 0; j < 4; j++) acc[nt][j] = 0.0f;

    // Phase-A mapping: 8-channel granule per thread
    const int pa_cg = t & 7;     // granule 0..7 (16B of fp16 = 8 channels)
    const int pa_p0 = t >> 3;    // pixel within pass (0..63)
    // Warp tile mapping (16 warps)
    const int wm = wid & 7;      // px group: 16*wm .. +15
    const int wn = wid >> 3;     // o  group: 32*wn .. +31
    // ldmatrix lane roles
    const int a_r  = lane & 15;
    const int a_q  = lane >> 4;
    const int b_or = (lane & 7) + ((lane >> 4) << 3);
    const int b_qb = (lane >> 3) & 1;

    __syncthreads();   // tables ready

    for (int k = 0; k < 9; k++) {
        const int buf = k & 1;
        char* a_buf = smem + (buf ? A1_OFF : A0_OFF);
        char* b_buf = smem + (buf ? B1_OFF : B0_OFF);

        // prefetch B_k into registers (hidden behind sampling)
        uint4 wb;
        {
            const uint4* sh = (const uint4*)g_wf + (size_t)k * 512;
            wb = __ldg(sh + t);
        }

        // ---- Phase A: fp16 gather + fp32 bilinear -> fp16 A tile (buf) ----
        const float4* pwk = s_pw + k * 128;
        const uint4*  pak = s_pa + k * 128;
#pragma unroll
        for (int pass = 0; pass < 2; pass++) {
            int p = pass * 64 + pa_p0;
            float4 w4 = pwk[p];
            uint4  a4 = pak[p];
            int cb = pa_cg * 16;   // granule byte offset (8 fp16 channels)

            uint4 u0 = __ldg((const uint4*)(xtb + a4.x + cb));
            uint4 u1 = __ldg((const uint4*)(xtb + a4.y + cb));
            uint4 u2 = __ldg((const uint4*)(xtb + a4.z + cb));
            uint4 u3 = __ldg((const uint4*)(xtb + a4.w + cb));

            uint32_t c0a[4] = {u0.x, u0.y, u0.z, u0.w};
            uint32_t c1a[4] = {u1.x, u1.y, u1.z, u1.w};
            uint32_t c2a[4] = {u2.x, u2.y, u2.z, u2.w};
            uint32_t c3a[4] = {u3.x, u3.y, u3.z, u3.w};

            float2 s[4];
#pragma unroll
            for (int j = 0; j < 4; j++) {
                float2 f = h2f2(c0a[j]);
                s[j].x = w4.x * f.x;
                s[j].y = w4.x * f.y;
            }
#pragma unroll
            for (int j = 0; j < 4; j++) {
                float2 f = h2f2(c1a[j]);
                s[j].x = fmaf(w4.y, f.x, s[j].x);
                s[j].y = fmaf(w4.y, f.y, s[j].y);
            }
#pragma unroll
            for (int j = 0; j < 4; j++) {
                float2 f = h2f2(c2a[j]);
                s[j].x = fmaf(w4.z, f.x, s[j].x);
                s[j].y = fmaf(w4.z, f.y, s[j].y);
            }
#pragma unroll
            for (int j = 0; j < 4; j++) {
                float2 f = h2f2(c3a[j]);
                s[j].x = fmaf(w4.w, f.x, s[j].x);
                s[j].y = fmaf(w4.w, f.y, s[j].y);
            }

            uint4 o;
            o.x = cvt2h(s[0].y, s[0].x);   // low half = lower channel
            o.y = cvt2h(s[1].y, s[1].x);
            o.z = cvt2h(s[2].y, s[2].x);
            o.w = cvt2h(s[3].y, s[3].x);

            int chunk = pa_cg ^ (p & 7);
            *(uint4*)(a_buf + p * 128 + chunk * 16) = o;
        }

        // store prefetched B (pre-swizzled layout): 512 threads x 16B = 8KB
        ((uint4*)b_buf)[t] = wb;

        __syncthreads();   // A(k), B(k) ready; also releases buf for k+2's writes

        // ---- Phase B: HMMA over 4 k-tiles, single fp16 term ----
        uint32_t a_base = sb + (buf ? A1_OFF : A0_OFF);
        uint32_t b_base = sb + (buf ? B1_OFF : B0_OFF);
#pragma unroll
        for (int kt = 0; kt < 4; kt++) {
            uint32_t af[4];
            {
                int row = wm * 16 + a_r;
                uint32_t ad = a_base + row * 128 +
                              (((2 * kt + a_q) ^ (a_r & 7)) * 16);
                LDMX4(af, ad);
            }
            uint32_t bf[2][4];
#pragma unroll
            for (int j = 0; j < 2; j++) {
                int o = wn * 32 + j * 16 + b_or;
                uint32_t bd = b_base + o * 128 +
                              (((2 * kt + b_qb) ^ (o & 7)) * 16);
                LDMX4(bf[j], bd);
            }
#pragma unroll
            for (int nt = 0; nt < 4; nt++) {
                const uint32_t* bp = &bf[nt >> 1][(nt & 1) * 2];
                MMA16816H(acc[nt], af, bp[0], bp[1]);
            }
        }
    }

    // ---- Epilogue: direct STG ----
    {
        int px = wm * 16 + (lane >> 2);
#pragma unroll
        for (int nt = 0; nt < 4; nt++) {
            int o0 = wn * 32 + nt * 8 + 2 * (lane & 3);
            float* ob = out + ((size_t)(b * 64 + o0)) * HW_ + (size_t)h * W_;
            ob[px]           = acc[nt][0];
            ob[HW_ + px]     = acc[nt][1];
            ob[px + 8]       = acc[nt][2];
            ob[HW_ + px + 8] = acc[nt][3];
        }
    }
}

// ---------------------------------------------------------------------------
extern "C" void kernel_launch(void* const* d_in, const int* in_sizes, int n_in,
                              void* d_out, int out_size) {
    const float* x     = (const float*)d_in[0];   // (8,64,128,128)
    const float* wght  = (const float*)d_in[1];   // (64,64,3,3)
    const float* w_off = (const float*)d_in[2];   // (18,64)
    const float* b_off = (const float*)d_in[3];   // (18,)
    float* out = (float*)d_out;                   // (8,64,128,128)

    k_prep<<<PREP_BLKS + K2_, 256>>>(x, w_off, b_off, wght);

    cudaFuncSetAttribute(k_main, cudaFuncAttributeMaxDynamicSharedMemorySize,
                         SMEM_SZ);
    k_main<<<B_ * H_, 512, SMEM_SZ>>>(out);
}